// round 2
// baseline (speedup 1.0000x reference)
#include <cuda_runtime.h>
#include <cstdint>

#define BATCH 16
#define NPTS  1024
#define FDIM  16
#define EDIM  12
#define HEADS 4
#define BB    32            // 2*BATCH (x-slab then y-slab)

// ---------------- scratch (device globals; no allocation allowed) ----------
__device__ float g_x3  [BATCH*NPTS*3];
__device__ float g_yt3 [BATCH*3];
__device__ float g_q_s [BB*HEADS*NPTS*4];      // pre-scaled q (stride 4)
__device__ float g_kv_s[BB*HEADS*NPTS*8];      // k0,k1,k2,v0,v1,v2,pad,pad
__device__ float g_oh_s[BB*NPTS*EDIM];         // per-head attn outputs, concat layout
__device__ float g_q_c [BATCH*HEADS*NPTS*4];
__device__ float g_kv_c[BATCH*HEADS*NPTS*8];
__device__ float g_oh_c[BATCH*NPTS*EDIM];
__device__ float g_stats[BATCH*16];            // S[9]=sum B_i*x_j, sumB[3], sumX[3]
__device__ float g_Rt  [BATCH*12];             // R[9], t[3]

__device__ __forceinline__ float ex2f(float x) {
    float y; asm("ex2.approx.ftz.f32 %0, %1;" : "=f"(y) : "f"(x)); return y;
}

// log2(e)/sqrt(3): fold softmax scale + base-2 conversion into Q
#define QSCALE ((float)(1.4426950408889634 / 1.7320508075688772))

// ============================================================================
// Kernel A: per (slab,batch): column means, center, input proj, self-QKV proj
// grid = 32 blocks (0..15 = x batches, 16..31 = y batches), 256 threads
// ============================================================================
__global__ __launch_bounds__(256) void prep_qkv_self(
    const float* __restrict__ x_orig, const float* __restrict__ y_orig,
    const float* __restrict__ W_in,   const float* __restrict__ b_in,
    const float* __restrict__ Wqkv_s, const float* __restrict__ bqkv_s)
{
    __shared__ float sW[EDIM*FDIM];
    __shared__ float sb[EDIM];
    __shared__ float sWq[36*EDIM];
    __shared__ float sbq[36];
    __shared__ float sred[256];
    __shared__ float smean[FDIM];

    const int tid  = threadIdx.x;
    const int s    = blockIdx.x;        // 0..31
    const int slab = s >> 4;            // 0 = x, 1 = y
    const int b    = s & 15;
    const float* in = (slab ? y_orig : x_orig) + (size_t)b * NPTS * FDIM;

    for (int i = tid; i < EDIM*FDIM; i += 256) sW[i]  = W_in[i];
    if (tid < EDIM) sb[tid] = b_in[tid];
    for (int i = tid; i < 36*EDIM;   i += 256) sWq[i] = Wqkv_s[i];
    if (tid < 36)   sbq[tid] = bqkv_s[tid];

    // column sums: thread (seg, f) sums 64 rows
    const int f = tid & 15, seg = tid >> 4;
    float acc = 0.f;
    for (int n = seg*64; n < seg*64 + 64; n++) acc += in[(size_t)n*FDIM + f];
    sred[tid] = acc;
    __syncthreads();
    if (tid < FDIM) {
        float m = 0.f;
        #pragma unroll
        for (int g = 0; g < 16; g++) m += sred[g*16 + tid];
        m *= (1.0f / NPTS);
        smean[tid] = m;
        if (slab && tid < 3) g_yt3[b*3 + tid] = m;
    }
    __syncthreads();

    for (int r = 0; r < 4; r++) {
        const int n = tid + r*256;
        const float4* rp = (const float4*)(in + (size_t)n*FDIM);
        float xr[FDIM];
        float4 v0 = rp[0], v1 = rp[1], v2 = rp[2], v3 = rp[3];
        xr[0]=v0.x; xr[1]=v0.y; xr[2]=v0.z; xr[3]=v0.w;
        xr[4]=v1.x; xr[5]=v1.y; xr[6]=v1.z; xr[7]=v1.w;
        xr[8]=v2.x; xr[9]=v2.y; xr[10]=v2.z; xr[11]=v2.w;
        xr[12]=v3.x; xr[13]=v3.y; xr[14]=v3.z; xr[15]=v3.w;
        #pragma unroll
        for (int k = 0; k < FDIM; k++) xr[k] -= smean[k];

        if (!slab) {
            float* p = g_x3 + ((size_t)b*NPTS + n)*3;
            p[0] = xr[0]; p[1] = xr[1]; p[2] = xr[2];
        }

        float z[EDIM];
        #pragma unroll
        for (int e = 0; e < EDIM; e++) {
            float a = sb[e];
            #pragma unroll
            for (int k = 0; k < FDIM; k++) a = fmaf(sW[e*FDIM + k], xr[k], a);
            z[e] = a;
        }

        float t[36];
        #pragma unroll
        for (int e2 = 0; e2 < 36; e2++) {
            float a = sbq[e2];
            #pragma unroll
            for (int e = 0; e < EDIM; e++) a = fmaf(sWq[e2*EDIM + e], z[e], a);
            t[e2] = a;
        }

        #pragma unroll
        for (int h = 0; h < HEADS; h++) {
            const size_t rowi = ((size_t)(s*HEADS + h) * NPTS + n);
            float* qp = g_q_s  + rowi*4;
            float* kp = g_kv_s + rowi*8;
            qp[0] = t[h*3+0]*QSCALE; qp[1] = t[h*3+1]*QSCALE; qp[2] = t[h*3+2]*QSCALE;
            kp[0] = t[12+h*3+0]; kp[1] = t[12+h*3+1]; kp[2] = t[12+h*3+2];
            kp[3] = t[24+h*3+0]; kp[4] = t[24+h*3+1]; kp[5] = t[24+h*3+2];
        }
    }
}

// ============================================================================
// Kernel B/D: attention. One block = (bh, tile), 256 threads, 2 queries/thread.
// CROSS=0 -> self arrays (nbh=128); CROSS=1 -> cross arrays (nbh=64)
// ============================================================================
template <int CROSS>
__global__ __launch_bounds__(256) void attn_kernel()
{
    const float* __restrict__ qg  = CROSS ? g_q_c  : g_q_s;
    const float* __restrict__ kvg = CROSS ? g_kv_c : g_kv_s;
    float*       __restrict__ oh  = CROSS ? g_oh_c : g_oh_s;

    __shared__ float4 skv[NPTS*2];           // 32 KB
    const int tid  = threadIdx.x;
    const int bh   = blockIdx.x >> 1;
    const int tile = blockIdx.x & 1;

    const float4* src = (const float4*)(kvg + (size_t)bh*NPTS*8);
    for (int i = tid; i < NPTS*2; i += 256) skv[i] = src[i];
    __syncthreads();

    const int n0 = tile*512 + tid;
    const int n1 = n0 + 256;
    const float* q0p = qg + ((size_t)bh*NPTS + n0)*4;
    const float* q1p = qg + ((size_t)bh*NPTS + n1)*4;
    const float q00=q0p[0], q01=q0p[1], q02=q0p[2];
    const float q10=q1p[0], q11=q1p[1], q12=q1p[2];

    float o00=0.f,o01=0.f,o02=0.f,l0=0.f;
    float o10=0.f,o11=0.f,o12=0.f,l1=0.f;

    #pragma unroll 4
    for (int j = 0; j < NPTS; j++) {
        const float4 a = skv[2*j];
        const float4 c = skv[2*j+1];
        float s0 = fmaf(q02, a.z, fmaf(q01, a.y, q00*a.x));
        float s1 = fmaf(q12, a.z, fmaf(q11, a.y, q10*a.x));
        float p0 = ex2f(s0);
        float p1 = ex2f(s1);
        o00 = fmaf(p0, a.w, o00); o01 = fmaf(p0, c.x, o01); o02 = fmaf(p0, c.y, o02); l0 += p0;
        o10 = fmaf(p1, a.w, o10); o11 = fmaf(p1, c.x, o11); o12 = fmaf(p1, c.y, o12); l1 += p1;
    }

    const int brow = bh >> 2, h = bh & 3;
    const float inv0 = 1.0f / l0, inv1 = 1.0f / l1;
    float* d0 = oh + ((size_t)brow*NPTS + n0)*EDIM + h*3;
    d0[0] = o00*inv0; d0[1] = o01*inv0; d0[2] = o02*inv0;
    float* d1 = oh + ((size_t)brow*NPTS + n1)*EDIM + h*3;
    d1[0] = o10*inv1; d1[1] = o11*inv1; d1[2] = o12*inv1;
}

// ============================================================================
// Kernel C: combine self-attn heads through Wo_s + bo_s, then cross-QKV proj.
// x-slab rows -> q_c, y-slab rows -> kv_c.  grid = 128 blocks x 256 threads
// ============================================================================
__global__ __launch_bounds__(256) void combine_qkv_cross(
    const float* __restrict__ Wo_s,   const float* __restrict__ bo_s,
    const float* __restrict__ Wqkv_c, const float* __restrict__ bqkv_c)
{
    __shared__ float sWo[EDIM*EDIM], sbo[EDIM], sWq[36*EDIM], sbq[36];
    const int tid = threadIdx.x;
    for (int i = tid; i < EDIM*EDIM; i += 256) sWo[i] = Wo_s[i];
    if (tid < EDIM) sbo[tid] = bo_s[tid];
    for (int i = tid; i < 36*EDIM; i += 256) sWq[i] = Wqkv_c[i];
    if (tid < 36) sbq[tid] = bqkv_c[tid];
    __syncthreads();

    const int row  = blockIdx.x*256 + tid;      // 0..32767
    const int slab = row >> 14;                 // all rows of a block share slab
    const int b    = (row >> 10) & 15;
    const int n    = row & 1023;

    const float* ohp = g_oh_s + (size_t)row*EDIM;
    float ohv[EDIM];
    #pragma unroll
    for (int k = 0; k < EDIM; k++) ohv[k] = ohp[k];

    float z[EDIM];
    #pragma unroll
    for (int e = 0; e < EDIM; e++) {
        float a = sbo[e];
        #pragma unroll
        for (int k = 0; k < EDIM; k++) a = fmaf(sWo[e*EDIM + k], ohv[k], a);
        z[e] = a;
    }

    if (slab == 0) {
        #pragma unroll
        for (int h = 0; h < HEADS; h++) {
            float* qp = g_q_c + ((size_t)(b*HEADS + h)*NPTS + n)*4;
            #pragma unroll
            for (int d = 0; d < 3; d++) {
                const int e2 = h*3 + d;
                float a = sbq[e2];
                #pragma unroll
                for (int e = 0; e < EDIM; e++) a = fmaf(sWq[e2*EDIM + e], z[e], a);
                qp[d] = a * QSCALE;
            }
        }
    } else {
        #pragma unroll
        for (int h = 0; h < HEADS; h++) {
            float* kp = g_kv_c + ((size_t)(b*HEADS + h)*NPTS + n)*8;
            #pragma unroll
            for (int d = 0; d < 3; d++) {
                const int e2k = 12 + h*3 + d;
                const int e2v = 24 + h*3 + d;
                float ak = sbq[e2k], av = sbq[e2v];
                #pragma unroll
                for (int e = 0; e < EDIM; e++) {
                    ak = fmaf(sWq[e2k*EDIM + e], z[e], ak);
                    av = fmaf(sWq[e2v*EDIM + e], z[e], av);
                }
                kp[d]   = ak;
                kp[3+d] = av;
            }
        }
    }
}

// ============================================================================
// Kernel E: combine cross heads (Wo_c), project to coords (W_out), accumulate
// Kabsch statistics per batch: S[i][j] = sum B_i * x_j (B = coords + x3),
// sumB, sumX.   grid = 16 blocks (one per batch), 256 threads x 4 rows
// ============================================================================
__global__ __launch_bounds__(256) void coords_stats(
    const float* __restrict__ Wo_c,  const float* __restrict__ bo_c,
    const float* __restrict__ W_out, const float* __restrict__ b_out)
{
    __shared__ float sWo[EDIM*EDIM], sbo[EDIM], sWt[3*EDIM], sbt[3];
    __shared__ float sred2[8][15];
    const int tid = threadIdx.x;
    const int b   = blockIdx.x;
    for (int i = tid; i < EDIM*EDIM; i += 256) sWo[i] = Wo_c[i];
    if (tid < EDIM)   sbo[tid] = bo_c[tid];
    if (tid < 3*EDIM) sWt[tid] = W_out[tid];
    if (tid < 3)      sbt[tid] = b_out[tid];
    __syncthreads();

    float S[9] = {0,0,0,0,0,0,0,0,0};
    float sB[3] = {0,0,0}, sX[3] = {0,0,0};

    for (int r = 0; r < 4; r++) {
        const int n = tid + 256*r;
        const float* ohp = g_oh_c + ((size_t)b*NPTS + n)*EDIM;
        float ohv[EDIM];
        #pragma unroll
        for (int k = 0; k < EDIM; k++) ohv[k] = ohp[k];

        float z[EDIM];
        #pragma unroll
        for (int e = 0; e < EDIM; e++) {
            float a = sbo[e];
            #pragma unroll
            for (int k = 0; k < EDIM; k++) a = fmaf(sWo[e*EDIM + k], ohv[k], a);
            z[e] = a;
        }
        float co[3];
        #pragma unroll
        for (int i = 0; i < 3; i++) {
            float a = sbt[i];
            #pragma unroll
            for (int e = 0; e < EDIM; e++) a = fmaf(sWt[i*EDIM + e], z[e], a);
            co[i] = a;
        }
        const float* xp = g_x3 + ((size_t)b*NPTS + n)*3;
        const float x0 = xp[0], x1 = xp[1], x2 = xp[2];
        const float B0 = co[0] + x0, B1 = co[1] + x1, B2 = co[2] + x2;
        S[0] += B0*x0; S[1] += B0*x1; S[2] += B0*x2;
        S[3] += B1*x0; S[4] += B1*x1; S[5] += B1*x2;
        S[6] += B2*x0; S[7] += B2*x1; S[8] += B2*x2;
        sB[0] += B0; sB[1] += B1; sB[2] += B2;
        sX[0] += x0; sX[1] += x1; sX[2] += x2;
    }

    float vals[15];
    #pragma unroll
    for (int k = 0; k < 9; k++) vals[k] = S[k];
    vals[9]=sB[0]; vals[10]=sB[1]; vals[11]=sB[2];
    vals[12]=sX[0]; vals[13]=sX[1]; vals[14]=sX[2];
    #pragma unroll
    for (int k = 0; k < 15; k++) {
        #pragma unroll
        for (int off = 16; off; off >>= 1)
            vals[k] += __shfl_xor_sync(0xffffffffu, vals[k], off);
    }
    const int lane = tid & 31, w = tid >> 5;
    if (lane == 0) {
        #pragma unroll
        for (int k = 0; k < 15; k++) sred2[w][k] = vals[k];
    }
    __syncthreads();
    if (tid < 15) {
        float a = 0.f;
        #pragma unroll
        for (int wi = 0; wi < 8; wi++) a += sred2[wi][tid];
        g_stats[b*16 + tid] = a;
    }
}

// ============================================================================
// Kernel F: Kabsch via Newton polar decomposition.
// Reference: A = coords+x3 (centroid cP), Bp = x3 (centroid cX ~= 0).
//   H[i][j] = sum (x3_i - cX_i)(A_j - cP_j) = S[j*3+i] - N*cX[i]*cP[j]
//   R = polar(H);  t = cP - cX @ R;  out = x3 @ R + t + yt3
// ============================================================================
__global__ void kabsch_kernel()
{
    const int b = threadIdx.x;
    if (b >= BATCH) return;
    const float* st = g_stats + b*16;
    float cP[3] = { st[9]*(1.0f/NPTS),  st[10]*(1.0f/NPTS), st[11]*(1.0f/NPTS) };
    float cX[3] = { st[12]*(1.0f/NPTS), st[13]*(1.0f/NPTS), st[14]*(1.0f/NPTS) };
    float X[9];
    #pragma unroll
    for (int i = 0; i < 3; i++)
        #pragma unroll
        for (int j = 0; j < 3; j++)
            X[i*3+j] = st[j*3+i] - (float)NPTS * cX[i] * cP[j];

    // normalize (polar factor is scale-invariant)
    float nf = 0.f;
    #pragma unroll
    for (int k = 0; k < 9; k++) nf += X[k]*X[k];
    const float inv = rsqrtf(nf);
    #pragma unroll
    for (int k = 0; k < 9; k++) X[k] *= inv;

    // Newton: X <- 0.5*(X + X^{-T});  X^{-T} = cof(X)/det(X)
    for (int it = 0; it < 12; it++) {
        float C[9];
        C[0] = X[4]*X[8] - X[5]*X[7];
        C[1] = X[5]*X[6] - X[3]*X[8];
        C[2] = X[3]*X[7] - X[4]*X[6];
        C[3] = X[2]*X[7] - X[1]*X[8];
        C[4] = X[0]*X[8] - X[2]*X[6];
        C[5] = X[1]*X[6] - X[0]*X[7];
        C[6] = X[1]*X[5] - X[2]*X[4];
        C[7] = X[2]*X[3] - X[0]*X[5];
        C[8] = X[0]*X[4] - X[1]*X[3];
        const float det = X[0]*C[0] + X[1]*C[1] + X[2]*C[2];
        const float hid = 0.5f / det;
        #pragma unroll
        for (int k = 0; k < 9; k++) X[k] = 0.5f*X[k] + C[k]*hid;
    }

    float* Rt = g_Rt + b*12;
    #pragma unroll
    for (int k = 0; k < 9; k++) Rt[k] = X[k];
    #pragma unroll
    for (int j = 0; j < 3; j++)
        Rt[9+j] = cP[j] - (cX[0]*X[0*3+j] + cX[1]*X[1*3+j] + cX[2]*X[2*3+j]);
}

// ============================================================================
// Kernel G: out = x3 @ R + t + y_t3     grid = 64 x 256
// ============================================================================
__global__ __launch_bounds__(256) void output_kernel(float* __restrict__ out)
{
    const int row = blockIdx.x*256 + threadIdx.x;   // < 16384
    const int b = row >> 10;
    const float* Rt = g_Rt + b*12;
    const float* yt = g_yt3 + b*3;
    const float* xp = g_x3 + (size_t)row*3;
    const float x0 = xp[0], x1 = xp[1], x2 = xp[2];
    #pragma unroll
    for (int j = 0; j < 3; j++) {
        out[(size_t)row*3 + j] =
            fmaf(x0, Rt[j], fmaf(x1, Rt[3+j], fmaf(x2, Rt[6+j], Rt[9+j] + yt[j])));
    }
}

// ============================================================================
extern "C" void kernel_launch(void* const* d_in, const int* in_sizes, int n_in,
                              void* d_out, int out_size)
{
    (void)in_sizes; (void)n_in; (void)out_size;
    const float* x_orig = (const float*)d_in[0];
    const float* y_orig = (const float*)d_in[1];
    const float* W_in   = (const float*)d_in[2];
    const float* b_in   = (const float*)d_in[3];
    const float* Wqkv_s = (const float*)d_in[4];
    const float* bqkv_s = (const float*)d_in[5];
    const float* Wo_s   = (const float*)d_in[6];
    const float* bo_s   = (const float*)d_in[7];
    const float* Wqkv_c = (const float*)d_in[8];
    const float* bqkv_c = (const float*)d_in[9];
    const float* Wo_c   = (const float*)d_in[10];
    const float* bo_c   = (const float*)d_in[11];
    const float* W_out  = (const float*)d_in[12];
    const float* b_out  = (const float*)d_in[13];
    float* out = (float*)d_out;

    prep_qkv_self<<<BB, 256>>>(x_orig, y_orig, W_in, b_in, Wqkv_s, bqkv_s);
    attn_kernel<0><<<BB*HEADS*2, 256>>>();                    // 256 blocks
    combine_qkv_cross<<<(BB*NPTS)/256, 256>>>(Wo_s, bo_s, Wqkv_c, bqkv_c);
    attn_kernel<1><<<BATCH*HEADS*2, 256>>>();                 // 128 blocks
    coords_stats<<<BATCH, 256>>>(Wo_c, bo_c, W_out, b_out);
    kabsch_kernel<<<1, 32>>>();
    output_kernel<<<(BATCH*NPTS)/256, 256>>>(out);
}

// round 4
// speedup vs baseline: 1.0050x; 1.0050x over previous
#include <cuda_runtime.h>
#include <cstdint>

#define BATCH 16
#define NPTS  1024
#define FDIM  16
#define EDIM  12
#define HEADS 4
#define BB    32            // 2*BATCH (x-slab then y-slab)

typedef unsigned long long u64;

// ---------------- scratch (device globals; no allocation allowed) ----------
__device__ float g_x3  [BATCH*NPTS*3];
__device__ float g_yt3 [BATCH*3];
__device__ float g_q_s [BB*HEADS*NPTS*4];       // pre-scaled q (stride 4)
__device__ float g_kv_s[BB*HEADS*NPTS*12];      // duplicated: k0k0 k1k1 k2k2 v0v0 v1v1 v2v2
__device__ float g_oh_s[BB*NPTS*EDIM];          // per-head attn outputs, concat layout
__device__ float g_q_c [BATCH*HEADS*NPTS*4];
__device__ float g_kv_c[BATCH*HEADS*NPTS*12];
__device__ float g_oh_c[BATCH*NPTS*EDIM];
__device__ float g_statp[BATCH*4*16];           // 4 partial stat sets per batch
__device__ float g_Rt  [BATCH*12];              // R[9], t[3]

__device__ __forceinline__ float ex2f(float x) {
    float y; asm("ex2.approx.ftz.f32 %0, %1;" : "=f"(y) : "f"(x)); return y;
}
__device__ __forceinline__ u64 ffma2(u64 a, u64 b, u64 c) {
    u64 d; asm("fma.rn.f32x2 %0, %1, %2, %3;" : "=l"(d) : "l"(a), "l"(b), "l"(c)); return d;
}
__device__ __forceinline__ u64 fmul2(u64 a, u64 b) {
    u64 d; asm("mul.rn.f32x2 %0, %1, %2;" : "=l"(d) : "l"(a), "l"(b)); return d;
}
__device__ __forceinline__ u64 fadd2(u64 a, u64 b) {
    u64 d; asm("add.rn.f32x2 %0, %1, %2;" : "=l"(d) : "l"(a), "l"(b)); return d;
}
__device__ __forceinline__ u64 pack2(float lo, float hi) {
    u64 d; asm("mov.b64 %0, {%1, %2};" : "=l"(d) : "f"(lo), "f"(hi)); return d;
}
__device__ __forceinline__ void unpack2(u64 v, float& lo, float& hi) {
    asm("mov.b64 {%0, %1}, %2;" : "=f"(lo), "=f"(hi) : "l"(v));
}

// log2(e)/sqrt(3): fold softmax scale + base-2 conversion into Q
#define QSCALE ((float)(1.4426950408889634 / 1.7320508075688772))

// ============================================================================
// Kernel A: per (slab,batch,quarter): column means (redundant per quarter),
// center, input proj, self-QKV proj.  grid = 128 blocks, 256 threads.
// ============================================================================
__global__ __launch_bounds__(256) void prep_qkv_self(
    const float* __restrict__ x_orig, const float* __restrict__ y_orig,
    const float* __restrict__ W_in,   const float* __restrict__ b_in,
    const float* __restrict__ Wqkv_s, const float* __restrict__ bqkv_s)
{
    __shared__ float sW[EDIM*FDIM];
    __shared__ float sb[EDIM];
    __shared__ float sWq[36*EDIM];
    __shared__ float sbq[36];
    __shared__ float sred[256];
    __shared__ float smean[FDIM];

    const int tid  = threadIdx.x;
    const int s    = blockIdx.x >> 2;   // 0..31
    const int quar = blockIdx.x & 3;
    const int slab = s >> 4;            // 0 = x, 1 = y
    const int b    = s & 15;
    const float* in = (slab ? y_orig : x_orig) + (size_t)b * NPTS * FDIM;

    for (int i = tid; i < EDIM*FDIM; i += 256) sW[i]  = W_in[i];
    if (tid < EDIM) sb[tid] = b_in[tid];
    for (int i = tid; i < 36*EDIM;   i += 256) sWq[i] = Wqkv_s[i];
    if (tid < 36)   sbq[tid] = bqkv_s[tid];

    // column sums: thread (seg, f) sums 64 rows
    const int f = tid & 15, seg = tid >> 4;
    float acc = 0.f;
    for (int n = seg*64; n < seg*64 + 64; n++) acc += in[(size_t)n*FDIM + f];
    sred[tid] = acc;
    __syncthreads();
    if (tid < FDIM) {
        float m = 0.f;
        #pragma unroll
        for (int g = 0; g < 16; g++) m += sred[g*16 + tid];
        m *= (1.0f / NPTS);
        smean[tid] = m;
        if (slab && quar == 0 && tid < 3) g_yt3[b*3 + tid] = m;
    }
    __syncthreads();

    const int n = quar*256 + tid;
    const float4* rp = (const float4*)(in + (size_t)n*FDIM);
    float xr[FDIM];
    float4 v0 = rp[0], v1 = rp[1], v2 = rp[2], v3 = rp[3];
    xr[0]=v0.x; xr[1]=v0.y; xr[2]=v0.z; xr[3]=v0.w;
    xr[4]=v1.x; xr[5]=v1.y; xr[6]=v1.z; xr[7]=v1.w;
    xr[8]=v2.x; xr[9]=v2.y; xr[10]=v2.z; xr[11]=v2.w;
    xr[12]=v3.x; xr[13]=v3.y; xr[14]=v3.z; xr[15]=v3.w;
    #pragma unroll
    for (int k = 0; k < FDIM; k++) xr[k] -= smean[k];

    if (!slab) {
        float* p = g_x3 + ((size_t)b*NPTS + n)*3;
        p[0] = xr[0]; p[1] = xr[1]; p[2] = xr[2];
    }

    float z[EDIM];
    #pragma unroll
    for (int e = 0; e < EDIM; e++) {
        float a = sb[e];
        #pragma unroll
        for (int k = 0; k < FDIM; k++) a = fmaf(sW[e*FDIM + k], xr[k], a);
        z[e] = a;
    }

    float t[36];
    #pragma unroll
    for (int e2 = 0; e2 < 36; e2++) {
        float a = sbq[e2];
        #pragma unroll
        for (int e = 0; e < EDIM; e++) a = fmaf(sWq[e2*EDIM + e], z[e], a);
        t[e2] = a;
    }

    #pragma unroll
    for (int h = 0; h < HEADS; h++) {
        const size_t rowi = ((size_t)(s*HEADS + h) * NPTS + n);
        float* qp = g_q_s  + rowi*4;
        float* kp = g_kv_s + rowi*12;
        qp[0] = t[h*3+0]*QSCALE; qp[1] = t[h*3+1]*QSCALE; qp[2] = t[h*3+2]*QSCALE;
        #pragma unroll
        for (int d = 0; d < 3; d++) {
            const float kv = t[12+h*3+d], vv = t[24+h*3+d];
            kp[2*d]   = kv; kp[2*d+1]   = kv;
            kp[6+2*d] = vv; kp[6+2*d+1] = vv;
        }
    }
}

// ============================================================================
// Kernel B/D: attention. One block = (bh, tile), 128 threads, 2 queries/thread
// packed as f32x2.  CROSS=0 -> self (bh=128, 512 blocks); CROSS=1 -> cross.
// ============================================================================
template <int CROSS>
__global__ __launch_bounds__(128) void attn_kernel()
{
    const float* __restrict__ qg  = CROSS ? g_q_c  : g_q_s;
    const float* __restrict__ kvg = CROSS ? g_kv_c : g_kv_s;
    float*       __restrict__ oh  = CROSS ? g_oh_c : g_oh_s;

    __shared__ float skv[NPTS*12];          // 48 KB duplicated KV
    const int tid  = threadIdx.x;
    const int bh   = blockIdx.x >> 2;
    const int tile = blockIdx.x & 3;

    {
        const float4* src = (const float4*)(kvg + (size_t)bh*NPTS*12);
        float4* dst = (float4*)skv;
        #pragma unroll
        for (int i = 0; i < NPTS*3/128; i++) dst[tid + i*128] = src[tid + i*128];
    }
    __syncthreads();

    const int n0 = tile*256 + tid;          // query 0
    const int n1 = n0 + 128;                // query 1
    const float* q0p = qg + ((size_t)bh*NPTS + n0)*4;
    const float* q1p = qg + ((size_t)bh*NPTS + n1)*4;
    const u64 q01_0 = pack2(q0p[0], q1p[0]);
    const u64 q01_1 = pack2(q0p[1], q1p[1]);
    const u64 q01_2 = pack2(q0p[2], q1p[2]);

    u64 o0 = 0ull, o1 = 0ull, o2 = 0ull, l = 0ull;   // (0.f,0.f)

    const ulonglong2* kp = (const ulonglong2*)skv;
    #pragma unroll 8
    for (int j = 0; j < NPTS; j++) {
        const ulonglong2 A = kp[3*j];       // (k0,k0) (k1,k1)
        const ulonglong2 Bq = kp[3*j+1];    // (k2,k2) (v0,v0)
        const ulonglong2 C = kp[3*j+2];     // (v1,v1) (v2,v2)
        u64 s01 = ffma2(q01_0, A.x, ffma2(q01_1, A.y, fmul2(q01_2, Bq.x)));
        float s0, s1; unpack2(s01, s0, s1);
        const u64 p01 = pack2(ex2f(s0), ex2f(s1));
        o0 = ffma2(p01, Bq.y, o0);
        o1 = ffma2(p01, C.x, o1);
        o2 = ffma2(p01, C.y, o2);
        l  = fadd2(l, p01);
    }

    float l0,l1, a00,a10, a01,a11, a02,a12;
    unpack2(l,  l0,  l1);
    unpack2(o0, a00, a10);
    unpack2(o1, a01, a11);
    unpack2(o2, a02, a12);

    const int brow = bh >> 2, h = bh & 3;
    const float inv0 = 1.0f / l0, inv1 = 1.0f / l1;
    float* d0 = oh + ((size_t)brow*NPTS + n0)*EDIM + h*3;
    d0[0] = a00*inv0; d0[1] = a01*inv0; d0[2] = a02*inv0;
    float* d1 = oh + ((size_t)brow*NPTS + n1)*EDIM + h*3;
    d1[0] = a10*inv1; d1[1] = a11*inv1; d1[2] = a12*inv1;
}

// ============================================================================
// Kernel C: combine self-attn heads through Wo_s + bo_s, then cross-QKV proj.
// x-slab rows -> q_c, y-slab rows -> kv_c.  grid = 128 blocks x 256 threads
// ============================================================================
__global__ __launch_bounds__(256) void combine_qkv_cross(
    const float* __restrict__ Wo_s,   const float* __restrict__ bo_s,
    const float* __restrict__ Wqkv_c, const float* __restrict__ bqkv_c)
{
    __shared__ float sWo[EDIM*EDIM], sbo[EDIM], sWq[36*EDIM], sbq[36];
    const int tid = threadIdx.x;
    for (int i = tid; i < EDIM*EDIM; i += 256) sWo[i] = Wo_s[i];
    if (tid < EDIM) sbo[tid] = bo_s[tid];
    for (int i = tid; i < 36*EDIM; i += 256) sWq[i] = Wqkv_c[i];
    if (tid < 36) sbq[tid] = bqkv_c[tid];
    __syncthreads();

    const int row  = blockIdx.x*256 + tid;      // 0..32767
    const int slab = row >> 14;                 // all rows of a block share slab
    const int b    = (row >> 10) & 15;
    const int n    = row & 1023;

    const float* ohp = g_oh_s + (size_t)row*EDIM;
    float ohv[EDIM];
    #pragma unroll
    for (int k = 0; k < EDIM; k++) ohv[k] = ohp[k];

    float z[EDIM];
    #pragma unroll
    for (int e = 0; e < EDIM; e++) {
        float a = sbo[e];
        #pragma unroll
        for (int k = 0; k < EDIM; k++) a = fmaf(sWo[e*EDIM + k], ohv[k], a);
        z[e] = a;
    }

    if (slab == 0) {
        #pragma unroll
        for (int h = 0; h < HEADS; h++) {
            float* qp = g_q_c + ((size_t)(b*HEADS + h)*NPTS + n)*4;
            #pragma unroll
            for (int d = 0; d < 3; d++) {
                const int e2 = h*3 + d;
                float a = sbq[e2];
                #pragma unroll
                for (int e = 0; e < EDIM; e++) a = fmaf(sWq[e2*EDIM + e], z[e], a);
                qp[d] = a * QSCALE;
            }
        }
    } else {
        #pragma unroll
        for (int h = 0; h < HEADS; h++) {
            float* kp = g_kv_c + ((size_t)(b*HEADS + h)*NPTS + n)*12;
            #pragma unroll
            for (int d = 0; d < 3; d++) {
                const int e2k = 12 + h*3 + d;
                const int e2v = 24 + h*3 + d;
                float ak = sbq[e2k], av = sbq[e2v];
                #pragma unroll
                for (int e = 0; e < EDIM; e++) {
                    ak = fmaf(sWq[e2k*EDIM + e], z[e], ak);
                    av = fmaf(sWq[e2v*EDIM + e], z[e], av);
                }
                kp[2*d]   = ak; kp[2*d+1]   = ak;
                kp[6+2*d] = av; kp[6+2*d+1] = av;
            }
        }
    }
}

// ============================================================================
// Kernel E: combine cross heads (Wo_c), project to coords (W_out), accumulate
// partial Kabsch statistics: S[i][j] = sum B_i*x_j (B = coords + x3), sumB, sumX.
// grid = 64 blocks (4 per batch), 256 threads, 1 row/thread.
// ============================================================================
__global__ __launch_bounds__(256) void coords_stats(
    const float* __restrict__ Wo_c,  const float* __restrict__ bo_c,
    const float* __restrict__ W_out, const float* __restrict__ b_out)
{
    __shared__ float sWo[EDIM*EDIM], sbo[EDIM], sWt[3*EDIM], sbt[3];
    __shared__ float sred2[8][15];
    const int tid  = threadIdx.x;
    const int b    = blockIdx.x >> 2;
    const int part = blockIdx.x & 3;
    for (int i = tid; i < EDIM*EDIM; i += 256) sWo[i] = Wo_c[i];
    if (tid < EDIM)   sbo[tid] = bo_c[tid];
    if (tid < 3*EDIM) sWt[tid] = W_out[tid];
    if (tid < 3)      sbt[tid] = b_out[tid];
    __syncthreads();

    const int n = part*256 + tid;
    const float* ohp = g_oh_c + ((size_t)b*NPTS + n)*EDIM;
    float ohv[EDIM];
    #pragma unroll
    for (int k = 0; k < EDIM; k++) ohv[k] = ohp[k];

    float z[EDIM];
    #pragma unroll
    for (int e = 0; e < EDIM; e++) {
        float a = sbo[e];
        #pragma unroll
        for (int k = 0; k < EDIM; k++) a = fmaf(sWo[e*EDIM + k], ohv[k], a);
        z[e] = a;
    }
    float co[3];
    #pragma unroll
    for (int i = 0; i < 3; i++) {
        float a = sbt[i];
        #pragma unroll
        for (int e = 0; e < EDIM; e++) a = fmaf(sWt[i*EDIM + e], z[e], a);
        co[i] = a;
    }
    const float* xp = g_x3 + ((size_t)b*NPTS + n)*3;
    const float x0 = xp[0], x1 = xp[1], x2 = xp[2];
    const float B0 = co[0] + x0, B1 = co[1] + x1, B2 = co[2] + x2;

    float vals[15];
    vals[0]=B0*x0; vals[1]=B0*x1; vals[2]=B0*x2;
    vals[3]=B1*x0; vals[4]=B1*x1; vals[5]=B1*x2;
    vals[6]=B2*x0; vals[7]=B2*x1; vals[8]=B2*x2;
    vals[9]=B0; vals[10]=B1; vals[11]=B2;
    vals[12]=x0; vals[13]=x1; vals[14]=x2;
    #pragma unroll
    for (int k = 0; k < 15; k++) {
        #pragma unroll
        for (int off = 16; off; off >>= 1)
            vals[k] += __shfl_xor_sync(0xffffffffu, vals[k], off);
    }
    const int lane = tid & 31, w = tid >> 5;
    if (lane == 0) {
        #pragma unroll
        for (int k = 0; k < 15; k++) sred2[w][k] = vals[k];
    }
    __syncthreads();
    if (tid < 15) {
        float a = 0.f;
        #pragma unroll
        for (int wi = 0; wi < 8; wi++) a += sred2[wi][tid];
        g_statp[(b*4 + part)*16 + tid] = a;
    }
}

// ============================================================================
// Kernel F: fold partials; Kabsch via Newton polar decomposition.
// Reference: A = coords+x3 (centroid cP), Bp = x3 (centroid cX).
//   H[i][j] = S[j*3+i] - N*cX[i]*cP[j];  R = polar(H);  t = cP - cX @ R
// ============================================================================
__global__ void kabsch_kernel()
{
    const int b = threadIdx.x;
    if (b >= BATCH) return;
    float st[15];
    #pragma unroll
    for (int k = 0; k < 15; k++) {
        float a = 0.f;
        #pragma unroll
        for (int p = 0; p < 4; p++) a += g_statp[(b*4 + p)*16 + k];
        st[k] = a;
    }
    float cP[3] = { st[9]*(1.0f/NPTS),  st[10]*(1.0f/NPTS), st[11]*(1.0f/NPTS) };
    float cX[3] = { st[12]*(1.0f/NPTS), st[13]*(1.0f/NPTS), st[14]*(1.0f/NPTS) };
    float X[9];
    #pragma unroll
    for (int i = 0; i < 3; i++)
        #pragma unroll
        for (int j = 0; j < 3; j++)
            X[i*3+j] = st[j*3+i] - (float)NPTS * cX[i] * cP[j];

    float nf = 0.f;
    #pragma unroll
    for (int k = 0; k < 9; k++) nf += X[k]*X[k];
    const float inv = rsqrtf(nf);
    #pragma unroll
    for (int k = 0; k < 9; k++) X[k] *= inv;

    for (int it = 0; it < 12; it++) {
        float C[9];
        C[0] = X[4]*X[8] - X[5]*X[7];
        C[1] = X[5]*X[6] - X[3]*X[8];
        C[2] = X[3]*X[7] - X[4]*X[6];
        C[3] = X[2]*X[7] - X[1]*X[8];
        C[4] = X[0]*X[8] - X[2]*X[6];
        C[5] = X[1]*X[6] - X[0]*X[7];
        C[6] = X[1]*X[5] - X[2]*X[4];
        C[7] = X[2]*X[3] - X[0]*X[5];
        C[8] = X[0]*X[4] - X[1]*X[3];
        const float det = X[0]*C[0] + X[1]*C[1] + X[2]*C[2];
        const float hid = 0.5f / det;
        #pragma unroll
        for (int k = 0; k < 9; k++) X[k] = 0.5f*X[k] + C[k]*hid;
    }

    float* Rt = g_Rt + b*12;
    #pragma unroll
    for (int k = 0; k < 9; k++) Rt[k] = X[k];
    #pragma unroll
    for (int j = 0; j < 3; j++)
        Rt[9+j] = cP[j] - (cX[0]*X[0*3+j] + cX[1]*X[1*3+j] + cX[2]*X[2*3+j]);
}

// ============================================================================
// Kernel G: out = x3 @ R + t + y_t3     grid = 64 x 256
// ============================================================================
__global__ __launch_bounds__(256) void output_kernel(float* __restrict__ out)
{
    const int row = blockIdx.x*256 + threadIdx.x;   // < 16384
    const int b = row >> 10;
    const float* Rt = g_Rt + b*12;
    const float* yt = g_yt3 + b*3;
    const float* xp = g_x3 + (size_t)row*3;
    const float x0 = xp[0], x1 = xp[1], x2 = xp[2];
    #pragma unroll
    for (int j = 0; j < 3; j++) {
        out[(size_t)row*3 + j] =
            fmaf(x0, Rt[j], fmaf(x1, Rt[3+j], fmaf(x2, Rt[6+j], Rt[9+j] + yt[j])));
    }
}

// ============================================================================
extern "C" void kernel_launch(void* const* d_in, const int* in_sizes, int n_in,
                              void* d_out, int out_size)
{
    (void)in_sizes; (void)n_in; (void)out_size;
    const float* x_orig = (const float*)d_in[0];
    const float* y_orig = (const float*)d_in[1];
    const float* W_in   = (const float*)d_in[2];
    const float* b_in   = (const float*)d_in[3];
    const float* Wqkv_s = (const float*)d_in[4];
    const float* bqkv_s = (const float*)d_in[5];
    const float* Wo_s   = (const float*)d_in[6];
    const float* bo_s   = (const float*)d_in[7];
    const float* Wqkv_c = (const float*)d_in[8];
    const float* bqkv_c = (const float*)d_in[9];
    const float* Wo_c   = (const float*)d_in[10];
    const float* bo_c   = (const float*)d_in[11];
    const float* W_out  = (const float*)d_in[12];
    const float* b_out  = (const float*)d_in[13];
    float* out = (float*)d_out;

    prep_qkv_self<<<BB*4, 256>>>(x_orig, y_orig, W_in, b_in, Wqkv_s, bqkv_s);
    attn_kernel<0><<<BB*HEADS*4, 128>>>();                    // 512 blocks
    combine_qkv_cross<<<(BB*NPTS)/256, 256>>>(Wo_s, bo_s, Wqkv_c, bqkv_c);
    attn_kernel<1><<<BATCH*HEADS*4, 128>>>();                 // 256 blocks
    coords_stats<<<BATCH*4, 256>>>(Wo_c, bo_c, W_out, b_out);
    kabsch_kernel<<<1, 32>>>();
    output_kernel<<<(BATCH*NPTS)/256, 256>>>(out);
}